// round 3
// baseline (speedup 1.0000x reference)
#include <cuda_runtime.h>
#include <cstdint>

// ---------------- problem constants ----------------
#define E_EXP   8
#define T_TOK   16384
#define D_MODEL 1024
#define F_FF    4096
#define M_PER_E (T_TOK / E_EXP)   // 2048

// ---------------- scratch (no allocs allowed) ----------------
__device__ float g_xr [(size_t)T_TOK * D_MODEL];          //  64MB  tf32-rounded X
__device__ float g_w1t[(size_t)E_EXP * F_FF * D_MODEL];   // 128MB  [E][F][D]
__device__ float g_w2t[(size_t)E_EXP * D_MODEL * F_FF];   // 128MB  [E][D][F]
__device__ float g_h  [(size_t)T_TOK * F_FF];             // 256MB  [T][F]

// ---------------- helpers ----------------
__device__ __forceinline__ float tf32r(float x) {
    uint32_t u;
    asm("cvt.rna.tf32.f32 %0, %1;" : "=r"(u) : "f"(x));
    return __uint_as_float(u);
}
__device__ __forceinline__ uint32_t smem_u32(const void* p) {
    uint32_t a;
    asm("{ .reg .u64 t; cvta.to.shared.u64 t, %1; cvt.u32.u64 %0, t; }" : "=r"(a) : "l"(p));
    return a;
}
#define CP_ASYNC_16(smem_addr, gmem_ptr) \
    asm volatile("cp.async.cg.shared.global [%0], [%1], 16;" \
                 :: "r"(smem_addr), "l"(gmem_ptr) : "memory")
#define CP_COMMIT() asm volatile("cp.async.commit_group;" ::: "memory")
#define CP_WAIT(n)  asm volatile("cp.async.wait_group %0;" :: "n"(n) : "memory")

__device__ __forceinline__ void mma_tf32_16n8k8(float* d, const uint32_t* a, const uint32_t* b) {
    asm volatile(
        "mma.sync.aligned.m16n8k8.row.col.f32.tf32.tf32.f32 "
        "{%0,%1,%2,%3}, {%4,%5,%6,%7}, {%8,%9}, {%0,%1,%2,%3};"
        : "+f"(d[0]), "+f"(d[1]), "+f"(d[2]), "+f"(d[3])
        : "r"(a[0]), "r"(a[1]), "r"(a[2]), "r"(a[3]), "r"(b[0]), "r"(b[1]));
}

__device__ __forceinline__ float gelu_tanh(float x) {
    float x3 = x * x * x;
    return 0.5f * x * (1.0f + tanhf(0.7978845608028654f * (x + 0.044715f * x3)));
}

// ---------------- prep kernels ----------------
__global__ void round_tf32_kernel(const float* __restrict__ src, float* __restrict__ dst) {
    size_t i = ((size_t)blockIdx.x * blockDim.x + threadIdx.x) * 4;
    float4 v = *(const float4*)(src + i);
    v.x = tf32r(v.x); v.y = tf32r(v.y); v.z = tf32r(v.z); v.w = tf32r(v.w);
    *(float4*)(dst + i) = v;
}

// transpose src[z][R][C] -> dst[z][C][R], rounding to tf32
__global__ void transpose_cvt_kernel(const float* __restrict__ src, float* __restrict__ dst,
                                     int R, int C) {
    __shared__ float t[32][33];
    size_t base = (size_t)blockIdx.z * R * C;
    int c0 = blockIdx.x * 32, r0 = blockIdx.y * 32;
    int tx = threadIdx.x, ty = threadIdx.y;
#pragma unroll
    for (int i = 0; i < 32; i += 8)
        t[ty + i][tx] = tf32r(src[base + (size_t)(r0 + ty + i) * C + c0 + tx]);
    __syncthreads();
#pragma unroll
    for (int i = 0; i < 32; i += 8)
        dst[base + (size_t)(c0 + ty + i) * R + r0 + tx] = t[tx][ty + i];
}

// ---------------- tf32 mma.sync GEMM ----------------
// C[M,N] = A[M,K] * Bt[N,K]^T  (+bias, optional GELU, optional tf32-round of output)
// Tiles: BM=128, BN=256, BK=32. 512 threads = 16 warps, warp grid 2(M) x 8(N),
// warp tile 64x32 -> 4 m-frags x 4 n-frags of m16n8k8. 3-stage cp.async pipeline.
#define BM 128
#define BN 256
#define BK 32
#define NTHREADS 512
#define NSTG 3
#define A_ST (BM * BK * 4)               // 16384 B / stage
#define B_ST (BN * BK * 4)               // 32768 B / stage
#define SM_B_OFF (NSTG * A_ST)           // 49152
#define SMEM_TOTAL (NSTG * (A_ST + B_ST))  // 147456

template <int APPLY_GELU, int ROUND_OUT>
__global__ void __launch_bounds__(NTHREADS, 1)
gemm_tf32_mma(const float* __restrict__ A, const float* __restrict__ Bt,
              const float* __restrict__ bias, float* __restrict__ Cm,
              int K, int N,
              long long aStride, long long bStride, int biasStride, long long cStride) {
    extern __shared__ char smem[];
    const uint32_t sb = smem_u32(smem);
    const int tid = threadIdx.x;
    const int wid = tid >> 5, lane = tid & 31;
    const int g = lane >> 2, tig = lane & 3;       // groupID, threadID-in-group
    const int wm = wid & 1, wn = wid >> 1;         // warp grid 2(M) x 8(N)
    const int e  = blockIdx.z;
    const int m0 = blockIdx.y * BM;
    const int n0 = blockIdx.x * BN;

    const float* Ae = A  + (long long)e * aStride + (long long)m0 * K;
    const float* Be = Bt + (long long)e * bStride + (long long)n0 * K;
    const float* be = bias + (long long)e * biasStride + n0;
    float* Ce = Cm + (long long)e * cStride;

    const int NK = K / BK;

    // ---- async copy of one stage ----
    auto issue_stage = [&](int kt, int slot) {
        const float* ag = Ae + kt * BK;
        const float* bg = Be + kt * BK;
        uint32_t sA = sb + slot * A_ST;
        uint32_t sB = sb + SM_B_OFF + slot * B_ST;
#pragma unroll
        for (int i = 0; i < 2; i++) {                  // A: 1024 x 16B chunks
            int c = tid + i * NTHREADS;
            int row = c >> 3, ch = c & 7;
            CP_ASYNC_16(sA + row * 128 + ((ch ^ (row & 7)) << 4),
                        ag + (long long)row * K + ch * 4);
        }
#pragma unroll
        for (int i = 0; i < 4; i++) {                  // B: 2048 x 16B chunks
            int c = tid + i * NTHREADS;
            int row = c >> 3, ch = c & 7;
            CP_ASYNC_16(sB + row * 128 + ((ch ^ (row & 7)) << 4),
                        bg + (long long)row * K + ch * 4);
        }
    };

    // prologue: stages 0, 1
    issue_stage(0, 0); CP_COMMIT();
    if (NK > 1) issue_stage(1, 1);
    CP_COMMIT();

    float acc[4][4][4];
#pragma unroll
    for (int mi = 0; mi < 4; mi++)
#pragma unroll
        for (int ni = 0; ni < 4; ni++)
#pragma unroll
            for (int j = 0; j < 4; j++) acc[mi][ni][j] = 0.0f;

    // per-lane constant address parts
    const uint32_t aLaneOff = (uint32_t)((wm * 64 + g) * 128 + tig * 4);  // + mi*2048 (+1024 for row+8)
    const uint32_t bLaneOff = (uint32_t)((wn * 32 + g) * 128 + tig * 4);  // + ni*1024

    for (int kt = 0; kt < NK; ++kt) {
        CP_WAIT(1);
        __syncthreads();
        if (kt + NSTG - 1 < NK) issue_stage(kt + NSTG - 1, (kt + NSTG - 1) % NSTG);
        CP_COMMIT();

        int slot = kt % NSTG;
        const char* stA = smem + slot * A_ST;
        const char* stB = smem + SM_B_OFF + slot * B_ST;

#pragma unroll
        for (int ks = 0; ks < 4; ks++) {
            const uint32_t ch0 = (uint32_t)(((2 * ks)     ^ g) << 4);
            const uint32_t ch1 = (uint32_t)(((2 * ks + 1) ^ g) << 4);
            uint32_t af[4][4];
#pragma unroll
            for (int mi = 0; mi < 4; mi++) {
                uint32_t base = aLaneOff + mi * 2048;
                af[mi][0] = *(const uint32_t*)(stA + base + ch0);
                af[mi][1] = *(const uint32_t*)(stA + base + 1024 + ch0);
                af[mi][2] = *(const uint32_t*)(stA + base + ch1);
                af[mi][3] = *(const uint32_t*)(stA + base + 1024 + ch1);
            }
            uint32_t bf[4][2];
#pragma unroll
            for (int ni = 0; ni < 4; ni++) {
                uint32_t base = bLaneOff + ni * 1024;
                bf[ni][0] = *(const uint32_t*)(stB + base + ch0);
                bf[ni][1] = *(const uint32_t*)(stB + base + ch1);
            }
#pragma unroll
            for (int mi = 0; mi < 4; mi++)
#pragma unroll
                for (int ni = 0; ni < 4; ni++)
                    mma_tf32_16n8k8(acc[mi][ni], af[mi], bf[ni]);
        }
        __syncthreads();
    }

    // ---- epilogue: bias (+GELU) (+tf32 round), direct float2 stores ----
#pragma unroll
    for (int ni = 0; ni < 4; ni++) {
        int colL = wn * 32 + ni * 8 + 2 * tig;
        float2 bb = *(const float2*)(be + colL);
#pragma unroll
        for (int mi = 0; mi < 4; mi++) {
            int rowL = m0 + wm * 64 + mi * 16 + g;
            float v0 = acc[mi][ni][0] + bb.x;
            float v1 = acc[mi][ni][1] + bb.y;
            float v2 = acc[mi][ni][2] + bb.x;
            float v3 = acc[mi][ni][3] + bb.y;
            if (APPLY_GELU) {
                v0 = gelu_tanh(v0); v1 = gelu_tanh(v1);
                v2 = gelu_tanh(v2); v3 = gelu_tanh(v3);
            }
            if (ROUND_OUT) {
                v0 = tf32r(v0); v1 = tf32r(v1); v2 = tf32r(v2); v3 = tf32r(v3);
            }
            float* p0 = Ce + (long long)rowL * N + n0 + colL;
            *(float2*)p0 = make_float2(v0, v1);
            *(float2*)(p0 + (long long)8 * N) = make_float2(v2, v3);
        }
    }
}

// ---------------- launch ----------------
extern "C" void kernel_launch(void* const* d_in, const int* in_sizes, int n_in,
                              void* d_out, int out_size) {
    (void)in_sizes; (void)n_in; (void)out_size;
    const float* x  = (const float*)d_in[0];
    // d_in[1] = expert_size (uniform T/E by construction; unused)
    const float* w1 = (const float*)d_in[2];
    const float* b1 = (const float*)d_in[3];
    const float* w2 = (const float*)d_in[4];
    const float* b2 = (const float*)d_in[5];
    float* out = (float*)d_out;

    float *xr, *w1t, *w2t, *h;
    cudaGetSymbolAddress((void**)&xr,  g_xr);
    cudaGetSymbolAddress((void**)&w1t, g_w1t);
    cudaGetSymbolAddress((void**)&w2t, g_w2t);
    cudaGetSymbolAddress((void**)&h,   g_h);

    cudaFuncSetAttribute(gemm_tf32_mma<1, 1>,
                         cudaFuncAttributeMaxDynamicSharedMemorySize, SMEM_TOTAL);
    cudaFuncSetAttribute(gemm_tf32_mma<0, 0>,
                         cudaFuncAttributeMaxDynamicSharedMemorySize, SMEM_TOTAL);

    // prep: round X, transpose+round weights
    round_tf32_kernel<<<(T_TOK * (size_t)D_MODEL) / (256 * 4), 256>>>(x, xr);
    dim3 tb(32, 8);
    transpose_cvt_kernel<<<dim3(F_FF / 32, D_MODEL / 32, E_EXP), tb>>>(w1, w1t, D_MODEL, F_FF);
    transpose_cvt_kernel<<<dim3(D_MODEL / 32, F_FF / 32, E_EXP), tb>>>(w2, w2t, F_FF, D_MODEL);

    // GEMM1: H = round(GELU(X @ W1 + b1))
    gemm_tf32_mma<1, 1><<<dim3(F_FF / BN, M_PER_E / BM, E_EXP), NTHREADS, SMEM_TOTAL>>>(
        xr, w1t, b1, h,
        /*K=*/D_MODEL, /*N=*/F_FF,
        (long long)M_PER_E * D_MODEL, (long long)F_FF * D_MODEL, F_FF,
        (long long)M_PER_E * F_FF);

    // GEMM2: Y = H @ W2 + b2
    gemm_tf32_mma<0, 0><<<dim3(D_MODEL / BN, M_PER_E / BM, E_EXP), NTHREADS, SMEM_TOTAL>>>(
        h, w2t, b2, out,
        /*K=*/F_FF, /*N=*/D_MODEL,
        (long long)M_PER_E * F_FF, (long long)D_MODEL * F_FF, D_MODEL,
        (long long)M_PER_E * D_MODEL);
}

// round 4
// speedup vs baseline: 2.0586x; 2.0586x over previous
#include <cuda_runtime.h>
#include <cuda_fp16.h>
#include <cstdint>

// ---------------- problem constants ----------------
#define E_EXP   8
#define T_TOK   16384
#define D_MODEL 1024
#define F_FF    4096
#define M_PER_E (T_TOK / E_EXP)   // 2048

// ---------------- scratch (no allocs allowed) ----------------
__device__ __half g_xh [(size_t)T_TOK * D_MODEL];          //  32MB  fp16 X
__device__ __half g_w1t[(size_t)E_EXP * F_FF * D_MODEL];   //  64MB  [E][F][D] fp16
__device__ __half g_w2t[(size_t)E_EXP * D_MODEL * F_FF];   //  64MB  [E][D][F] fp16
__device__ __half g_h  [(size_t)T_TOK * F_FF];             // 128MB  [T][F]    fp16

// ---------------- helpers ----------------
__device__ __forceinline__ uint32_t smem_u32(const void* p) {
    uint32_t a;
    asm("{ .reg .u64 t; cvta.to.shared.u64 t, %1; cvt.u32.u64 %0, t; }" : "=r"(a) : "l"(p));
    return a;
}
#define CP_ASYNC_16(smem_addr, gmem_ptr) \
    asm volatile("cp.async.cg.shared.global [%0], [%1], 16;" \
                 :: "r"(smem_addr), "l"(gmem_ptr) : "memory")
#define CP_COMMIT() asm volatile("cp.async.commit_group;" ::: "memory")
#define CP_WAIT(n)  asm volatile("cp.async.wait_group %0;" :: "n"(n) : "memory")

__device__ __forceinline__ void ldsm_x4(uint32_t* r, uint32_t addr) {
    asm volatile("ldmatrix.sync.aligned.m8n8.x4.shared.b16 {%0,%1,%2,%3}, [%4];"
                 : "=r"(r[0]), "=r"(r[1]), "=r"(r[2]), "=r"(r[3]) : "r"(addr));
}

__device__ __forceinline__ void mma_f16_16n8k16(float* d, const uint32_t* a, const uint32_t* b) {
    asm volatile(
        "mma.sync.aligned.m16n8k16.row.col.f32.f16.f16.f32 "
        "{%0,%1,%2,%3}, {%4,%5,%6,%7}, {%8,%9}, {%0,%1,%2,%3};"
        : "+f"(d[0]), "+f"(d[1]), "+f"(d[2]), "+f"(d[3])
        : "r"(a[0]), "r"(a[1]), "r"(a[2]), "r"(a[3]), "r"(b[0]), "r"(b[1]));
}

__device__ __forceinline__ float gelu_tanh(float x) {
    float x3 = x * x * x;
    return 0.5f * x * (1.0f + tanhf(0.7978845608028654f * (x + 0.044715f * x3)));
}

// ---------------- prep kernels ----------------
// fp32 -> fp16, 4 elems/thread
__global__ void cvt_half_kernel(const float* __restrict__ src, __half* __restrict__ dst) {
    size_t i = ((size_t)blockIdx.x * blockDim.x + threadIdx.x) * 4;
    float4 v = *(const float4*)(src + i);
    __half2 h0 = __floats2half2_rn(v.x, v.y);
    __half2 h1 = __floats2half2_rn(v.z, v.w);
    *(__half2*)(dst + i) = h0;
    *(__half2*)(dst + i + 2) = h1;
}

// transpose src[z][R][C] fp32 -> dst[z][C][R] fp16
__global__ void transpose_cvt_half(const float* __restrict__ src, __half* __restrict__ dst,
                                   int R, int C) {
    __shared__ float t[32][33];
    size_t base = (size_t)blockIdx.z * R * C;
    int c0 = blockIdx.x * 32, r0 = blockIdx.y * 32;
    int tx = threadIdx.x, ty = threadIdx.y;
#pragma unroll
    for (int i = 0; i < 32; i += 8)
        t[ty + i][tx] = src[base + (size_t)(r0 + ty + i) * C + c0 + tx];
    __syncthreads();
#pragma unroll
    for (int i = 0; i < 32; i += 8)
        dst[base + (size_t)(c0 + ty + i) * R + r0 + tx] = __float2half_rn(t[tx][ty + i]);
}

// ---------------- fp16 mma.sync GEMM ----------------
// C[M,N] = A[M,K] * Bt[N,K]^T  (+bias, optional GELU; OUT_HALF selects fp16 vs fp32 out)
// BM=128, BN=256, BK=64 (fp16). 512 threads = 16 warps, warp grid 2(M) x 8(N),
// warp tile 64x32 -> 4 m-frags x 4 n-frags of m16n8k16. ldmatrix.x4 fragment loads.
#define BM 128
#define BN 256
#define BK 64
#define NTHREADS 512
#define NSTG 3
#define A_ST (BM * BK * 2)               // 16384 B / stage
#define B_ST (BN * BK * 2)               // 32768 B / stage
#define SM_B_OFF (NSTG * A_ST)           // 49152
#define SMEM_TOTAL (NSTG * (A_ST + B_ST))  // 147456

template <int APPLY_GELU, int OUT_HALF>
__global__ void __launch_bounds__(NTHREADS, 1)
gemm_f16_mma(const __half* __restrict__ A, const __half* __restrict__ Bt,
             const float* __restrict__ bias, void* __restrict__ Cv,
             int K, int N,
             long long aStride, long long bStride, int biasStride, long long cStride) {
    extern __shared__ char smem[];
    const uint32_t sb = smem_u32(smem);
    const int tid = threadIdx.x;
    const int wid = tid >> 5, lane = tid & 31;
    const int g = lane >> 2, tig = lane & 3;
    const int wm = wid & 1, wn = wid >> 1;         // warp grid 2(M) x 8(N)
    const int e  = blockIdx.z;
    const int m0 = blockIdx.y * BM;
    const int n0 = blockIdx.x * BN;

    const __half* Ae = A  + (long long)e * aStride + (long long)m0 * K;
    const __half* Be = Bt + (long long)e * bStride + (long long)n0 * K;
    const float*  be = bias + (long long)e * biasStride + n0;

    const int NK = K / BK;

    // ---- async copy of one stage (rows of 128B = 8 x 16B chunks, XOR swizzle) ----
    auto issue_stage = [&](int kt, int slot) {
        const __half* ag = Ae + kt * BK;
        const __half* bg = Be + kt * BK;
        uint32_t sA = sb + slot * A_ST;
        uint32_t sB = sb + SM_B_OFF + slot * B_ST;
#pragma unroll
        for (int i = 0; i < 2; i++) {                  // A: 1024 x 16B chunks
            int c = tid + i * NTHREADS;
            int row = c >> 3, ch = c & 7;
            CP_ASYNC_16(sA + row * 128 + ((ch ^ (row & 7)) << 4),
                        ag + (long long)row * K + ch * 8);
        }
#pragma unroll
        for (int i = 0; i < 4; i++) {                  // B: 2048 x 16B chunks
            int c = tid + i * NTHREADS;
            int row = c >> 3, ch = c & 7;
            CP_ASYNC_16(sB + row * 128 + ((ch ^ (row & 7)) << 4),
                        bg + (long long)row * K + ch * 8);
        }
    };

    issue_stage(0, 0); CP_COMMIT();
    if (NK > 1) issue_stage(1, 1);
    CP_COMMIT();

    float acc[4][4][4];
#pragma unroll
    for (int mi = 0; mi < 4; mi++)
#pragma unroll
        for (int ni = 0; ni < 4; ni++)
#pragma unroll
            for (int j = 0; j < 4; j++) acc[mi][ni][j] = 0.0f;

    // ldmatrix lane address components
    const int aRowL = lane & 15;               // 0..15 within m16 tile
    const int aKC   = lane >> 4;               // 0/1 -> k chunk lo/hi
    const int bRowL = ((lane >> 4) << 3) + (lane & 7);  // 0..15 within n16 pair
    const int bKC   = (lane >> 3) & 1;
    const uint32_t aSw = (uint32_t)(aRowL & 7);
    const uint32_t bSw = (uint32_t)(lane & 7);
    uint32_t aRowOff[4], bRowOff[2];
#pragma unroll
    for (int mi = 0; mi < 4; mi++)
        aRowOff[mi] = (uint32_t)((wm * 64 + mi * 16 + aRowL) * 128);
#pragma unroll
    for (int p = 0; p < 2; p++)
        bRowOff[p] = (uint32_t)((wn * 32 + p * 16 + bRowL) * 128);

    for (int kt = 0; kt < NK; ++kt) {
        CP_WAIT(1);
        __syncthreads();
        if (kt + NSTG - 1 < NK) issue_stage(kt + NSTG - 1, (kt + NSTG - 1) % NSTG);
        CP_COMMIT();

        int slot = kt % NSTG;
        uint32_t sA = sb + slot * A_ST;
        uint32_t sB = sb + SM_B_OFF + slot * B_ST;

#pragma unroll
        for (int ks = 0; ks < 4; ks++) {               // 4 x K=16 steps
            uint32_t af[4][4], bf[4][2];
            {
                uint32_t chA = (uint32_t)(2 * ks + aKC);
#pragma unroll
                for (int mi = 0; mi < 4; mi++)
                    ldsm_x4(af[mi], sA + aRowOff[mi] + (((chA ^ aSw)) << 4));
                uint32_t chB = (uint32_t)(2 * ks + bKC);
#pragma unroll
                for (int p = 0; p < 2; p++) {
                    uint32_t r[4];
                    ldsm_x4(r, sB + bRowOff[p] + (((chB ^ bSw)) << 4));
                    bf[2 * p][0] = r[0]; bf[2 * p][1] = r[1];
                    bf[2 * p + 1][0] = r[2]; bf[2 * p + 1][1] = r[3];
                }
            }
#pragma unroll
            for (int mi = 0; mi < 4; mi++)
#pragma unroll
                for (int ni = 0; ni < 4; ni++)
                    mma_f16_16n8k16(acc[mi][ni], af[mi], bf[ni]);
        }
        __syncthreads();
    }

    // ---- epilogue ----
#pragma unroll
    for (int ni = 0; ni < 4; ni++) {
        int colL = wn * 32 + ni * 8 + 2 * tig;
        float2 bb = *(const float2*)(be + colL);
#pragma unroll
        for (int mi = 0; mi < 4; mi++) {
            int rowL = m0 + wm * 64 + mi * 16 + g;
            float v0 = acc[mi][ni][0] + bb.x;
            float v1 = acc[mi][ni][1] + bb.y;
            float v2 = acc[mi][ni][2] + bb.x;
            float v3 = acc[mi][ni][3] + bb.y;
            if (APPLY_GELU) {
                v0 = gelu_tanh(v0); v1 = gelu_tanh(v1);
                v2 = gelu_tanh(v2); v3 = gelu_tanh(v3);
            }
            if (OUT_HALF) {
                __half* Ce = (__half*)Cv + (long long)e * cStride;
                __half* p0 = Ce + (long long)rowL * N + n0 + colL;
                *(__half2*)p0 = __floats2half2_rn(v0, v1);
                *(__half2*)(p0 + (long long)8 * N) = __floats2half2_rn(v2, v3);
            } else {
                float* Ce = (float*)Cv + (long long)e * cStride;
                float* p0 = Ce + (long long)rowL * N + n0 + colL;
                *(float2*)p0 = make_float2(v0, v1);
                *(float2*)(p0 + (long long)8 * N) = make_float2(v2, v3);
            }
        }
    }
}

// ---------------- launch ----------------
extern "C" void kernel_launch(void* const* d_in, const int* in_sizes, int n_in,
                              void* d_out, int out_size) {
    (void)in_sizes; (void)n_in; (void)out_size;
    const float* x  = (const float*)d_in[0];
    // d_in[1] = expert_size (uniform T/E by construction; unused)
    const float* w1 = (const float*)d_in[2];
    const float* b1 = (const float*)d_in[3];
    const float* w2 = (const float*)d_in[4];
    const float* b2 = (const float*)d_in[5];
    float* out = (float*)d_out;

    __half *xh, *w1t, *w2t, *h;
    cudaGetSymbolAddress((void**)&xh,  g_xh);
    cudaGetSymbolAddress((void**)&w1t, g_w1t);
    cudaGetSymbolAddress((void**)&w2t, g_w2t);
    cudaGetSymbolAddress((void**)&h,   g_h);

    cudaFuncSetAttribute(gemm_f16_mma<1, 1>,
                         cudaFuncAttributeMaxDynamicSharedMemorySize, SMEM_TOTAL);
    cudaFuncSetAttribute(gemm_f16_mma<0, 0>,
                         cudaFuncAttributeMaxDynamicSharedMemorySize, SMEM_TOTAL);

    // prep: convert X, transpose+convert weights
    cvt_half_kernel<<<(T_TOK * (size_t)D_MODEL) / (256 * 4), 256>>>(x, xh);
    dim3 tb(32, 8);
    transpose_cvt_half<<<dim3(F_FF / 32, D_MODEL / 32, E_EXP), tb>>>(w1, w1t, D_MODEL, F_FF);
    transpose_cvt_half<<<dim3(D_MODEL / 32, F_FF / 32, E_EXP), tb>>>(w2, w2t, F_FF, D_MODEL);

    // GEMM1: H = half(GELU(X @ W1 + b1))
    gemm_f16_mma<1, 1><<<dim3(F_FF / BN, M_PER_E / BM, E_EXP), NTHREADS, SMEM_TOTAL>>>(
        xh, w1t, b1, h,
        /*K=*/D_MODEL, /*N=*/F_FF,
        (long long)M_PER_E * D_MODEL, (long long)F_FF * D_MODEL, F_FF,
        (long long)M_PER_E * F_FF);

    // GEMM2: Y = H @ W2 + b2 (fp32 out)
    gemm_f16_mma<0, 0><<<dim3(D_MODEL / BN, M_PER_E / BM, E_EXP), NTHREADS, SMEM_TOTAL>>>(
        h, w2t, b2, out,
        /*K=*/F_FF, /*N=*/D_MODEL,
        (long long)M_PER_E * F_FF, (long long)D_MODEL * F_FF, D_MODEL,
        (long long)M_PER_E * D_MODEL);
}

// round 5
// speedup vs baseline: 2.0692x; 1.0051x over previous
#include <cuda_runtime.h>
#include <cuda_fp16.h>
#include <cstdint>

// ---------------- problem constants ----------------
#define E_EXP   8
#define T_TOK   16384
#define D_MODEL 1024
#define F_FF    4096
#define M_PER_E (T_TOK / E_EXP)   // 2048

// ---------------- scratch (no allocs allowed) ----------------
__device__ __half g_xh [(size_t)T_TOK * D_MODEL];          //  32MB  fp16 X
__device__ __half g_w1t[(size_t)E_EXP * F_FF * D_MODEL];   //  64MB  [E][F][D] fp16
__device__ __half g_w2t[(size_t)E_EXP * D_MODEL * F_FF];   //  64MB  [E][D][F] fp16
__device__ __half g_h  [(size_t)T_TOK * F_FF];             // 128MB  [T][F]    fp16

// ---------------- helpers ----------------
__device__ __forceinline__ uint32_t smem_u32(const void* p) {
    uint32_t a;
    asm("{ .reg .u64 t; cvta.to.shared.u64 t, %1; cvt.u32.u64 %0, t; }" : "=r"(a) : "l"(p));
    return a;
}
#define CP_ASYNC_16(smem_addr, gmem_ptr) \
    asm volatile("cp.async.cg.shared.global [%0], [%1], 16;" \
                 :: "r"(smem_addr), "l"(gmem_ptr) : "memory")
#define CP_COMMIT() asm volatile("cp.async.commit_group;" ::: "memory")
#define CP_WAIT(n)  asm volatile("cp.async.wait_group %0;" :: "n"(n) : "memory")

__device__ __forceinline__ void ldsm_x4(uint32_t* r, uint32_t addr) {
    asm volatile("ldmatrix.sync.aligned.m8n8.x4.shared.b16 {%0,%1,%2,%3}, [%4];"
                 : "=r"(r[0]), "=r"(r[1]), "=r"(r[2]), "=r"(r[3]) : "r"(addr));
}

__device__ __forceinline__ void mma_f16_16n8k16(float* d, const uint32_t* a, const uint32_t* b) {
    asm volatile(
        "mma.sync.aligned.m16n8k16.row.col.f32.f16.f16.f32 "
        "{%0,%1,%2,%3}, {%4,%5,%6,%7}, {%8,%9}, {%0,%1,%2,%3};"
        : "+f"(d[0]), "+f"(d[1]), "+f"(d[2]), "+f"(d[3])
        : "r"(a[0]), "r"(a[1]), "r"(a[2]), "r"(a[3]), "r"(b[0]), "r"(b[1]));
}

__device__ __forceinline__ float gelu_tanh(float x) {
    float x3 = x * x * x;
    return 0.5f * x * (1.0f + tanhf(0.7978845608028654f * (x + 0.044715f * x3)));
}

// ---------------- prep kernels ----------------
__global__ void cvt_half_kernel(const float* __restrict__ src, __half* __restrict__ dst) {
    size_t i = ((size_t)blockIdx.x * blockDim.x + threadIdx.x) * 4;
    float4 v = *(const float4*)(src + i);
    *(__half2*)(dst + i)     = __floats2half2_rn(v.x, v.y);
    *(__half2*)(dst + i + 2) = __floats2half2_rn(v.z, v.w);
}

// transpose src[z][R][C] fp32 -> dst[z][C][R] fp16
__global__ void transpose_cvt_half(const float* __restrict__ src, __half* __restrict__ dst,
                                   int R, int C) {
    __shared__ float t[32][33];
    size_t base = (size_t)blockIdx.z * R * C;
    int c0 = blockIdx.x * 32, r0 = blockIdx.y * 32;
    int tx = threadIdx.x, ty = threadIdx.y;
#pragma unroll
    for (int i = 0; i < 32; i += 8)
        t[ty + i][tx] = src[base + (size_t)(r0 + ty + i) * C + c0 + tx];
    __syncthreads();
#pragma unroll
    for (int i = 0; i < 32; i += 8)
        dst[base + (size_t)(c0 + ty + i) * R + r0 + tx] = __float2half_rn(t[tx][ty + i]);
}

// ---------------- fp16 mma.sync GEMM ----------------
// C[M,N] = A[M,K] * Bt[N,K]^T  (+bias, optional GELU; OUT_HALF fp16 vs fp32 out)
// BM=128, BN=256, BK=64. 512 threads = 16 warps, warp grid 2(M) x 8(N),
// warp tile 64x32 -> 4 m x 4 n frags of m16n8k16. ldmatrix.x4, hoisted addressing.
#define BM 128
#define BN 256
#define BK 64
#define NTHREADS 512
#define NSTG 3
#define A_ST (BM * BK * 2)               // 16384 B / stage
#define B_ST (BN * BK * 2)               // 32768 B / stage
#define SM_B_OFF (NSTG * A_ST)           // 49152
#define SMEM_TOTAL (NSTG * (A_ST + B_ST))  // 147456

template <int APPLY_GELU, int OUT_HALF>
__global__ void __launch_bounds__(NTHREADS, 1)
gemm_f16_mma(const __half* __restrict__ A, const __half* __restrict__ Bt,
             const float* __restrict__ bias, void* __restrict__ Cv,
             int K, int N,
             long long aStride, long long bStride, int biasStride, long long cStride) {
    extern __shared__ char smem[];
    const uint32_t sb = smem_u32(smem);
    const int tid = threadIdx.x;
    const int wid = tid >> 5, lane = tid & 31;
    const int g = lane >> 2, tig = lane & 3;
    const int wm = wid & 1, wn = wid >> 1;         // warp grid 2(M) x 8(N)
    const int e  = blockIdx.z;
    const int m0 = blockIdx.y * BM;
    const int n0 = blockIdx.x * BN;

    const __half* Ae = A  + (long long)e * aStride + (long long)m0 * K;
    const __half* Be = Bt + (long long)e * bStride + (long long)n0 * K;
    const float*  be = bias + (long long)e * biasStride + n0;

    const int NK = K / BK;

    // ---- async copy of one stage (rows of 128B = 8 x 16B chunks, XOR swizzle) ----
    auto issue_stage = [&](int kt, int slot) {
        const __half* ag = Ae + kt * BK;
        const __half* bg = Be + kt * BK;
        uint32_t sA = sb + slot * A_ST;
        uint32_t sB = sb + SM_B_OFF + slot * B_ST;
#pragma unroll
        for (int i = 0; i < 2; i++) {                  // A: 1024 x 16B chunks
            int c = tid + i * NTHREADS;
            int row = c >> 3, ch = c & 7;
            CP_ASYNC_16(sA + row * 128 + ((ch ^ (row & 7)) << 4),
                        ag + (long long)row * K + ch * 8);
        }
#pragma unroll
        for (int i = 0; i < 4; i++) {                  // B: 2048 x 16B chunks
            int c = tid + i * NTHREADS;
            int row = c >> 3, ch = c & 7;
            CP_ASYNC_16(sB + row * 128 + ((ch ^ (row & 7)) << 4),
                        bg + (long long)row * K + ch * 8);
        }
    };

    issue_stage(0, 0); CP_COMMIT();
    if (NK > 1) issue_stage(1, 1);
    CP_COMMIT();

    float acc[4][4][4];
#pragma unroll
    for (int mi = 0; mi < 4; mi++)
#pragma unroll
        for (int ni = 0; ni < 4; ni++)
#pragma unroll
            for (int j = 0; j < 4; j++) acc[mi][ni][j] = 0.0f;

    // ---- hoisted per-lane ldmatrix addressing ----
    const int aRowL = lane & 15;                        // row within m16 tile
    const int aKC   = lane >> 4;                        // k-chunk lo/hi
    const int bRowL = ((lane >> 4) << 3) + (lane & 7);  // row within n16 pair
    const int bKC   = (lane >> 3) & 1;
    // loop-invariant swizzled chunk offsets per k-step
    uint32_t aChunkOff[4], bChunkOff[4];
#pragma unroll
    for (int ks = 0; ks < 4; ks++) {
        aChunkOff[ks] = (uint32_t)(((2 * ks + aKC) ^ (aRowL & 7)) << 4);
        bChunkOff[ks] = (uint32_t)(((2 * ks + bKC) ^ (lane & 7)) << 4);
    }
    // loop-invariant row offsets (relative to stage base)
    uint32_t aRowOff[4], bRowOff[2];
#pragma unroll
    for (int mi = 0; mi < 4; mi++)
        aRowOff[mi] = (uint32_t)((wm * 64 + mi * 16 + aRowL) * 128);
#pragma unroll
    for (int p = 0; p < 2; p++)
        bRowOff[p] = (uint32_t)((wn * 32 + p * 16 + bRowL) * 128);

    for (int kt = 0; kt < NK; ++kt) {
        CP_WAIT(1);
        __syncthreads();
        // Safe: slot (kt+NSTG-1)%NSTG was last read in iteration kt-1, which
        // completed before the barrier above in all warps.
        if (kt + NSTG - 1 < NK) issue_stage(kt + NSTG - 1, (kt + NSTG - 1) % NSTG);
        CP_COMMIT();

        int slot = kt % NSTG;
        uint32_t aBase[4], bBase[2];
#pragma unroll
        for (int mi = 0; mi < 4; mi++) aBase[mi] = sb + slot * A_ST + aRowOff[mi];
#pragma unroll
        for (int p = 0; p < 2; p++)    bBase[p]  = sb + SM_B_OFF + slot * B_ST + bRowOff[p];

#pragma unroll
        for (int ks = 0; ks < 4; ks++) {               // 4 x K=16 steps
            uint32_t af[4][4], bf[4][2];
#pragma unroll
            for (int mi = 0; mi < 4; mi++)
                ldsm_x4(af[mi], aBase[mi] + aChunkOff[ks]);
#pragma unroll
            for (int p = 0; p < 2; p++) {
                uint32_t r[4];
                ldsm_x4(r, bBase[p] + bChunkOff[ks]);
                bf[2 * p][0] = r[0]; bf[2 * p][1] = r[1];
                bf[2 * p + 1][0] = r[2]; bf[2 * p + 1][1] = r[3];
            }
#pragma unroll
            for (int mi = 0; mi < 4; mi++)
#pragma unroll
                for (int ni = 0; ni < 4; ni++)
                    mma_f16_16n8k16(acc[mi][ni], af[mi], bf[ni]);
        }
        // no trailing barrier needed: next iteration's top barrier orders
        // this iteration's fragment reads before any overwrite of this slot.
    }

    // ---- epilogue ----
#pragma unroll
    for (int ni = 0; ni < 4; ni++) {
        int colL = wn * 32 + ni * 8 + 2 * tig;
        float2 bb = *(const float2*)(be + colL);
#pragma unroll
        for (int mi = 0; mi < 4; mi++) {
            int rowL = m0 + wm * 64 + mi * 16 + g;
            float v0 = acc[mi][ni][0] + bb.x;
            float v1 = acc[mi][ni][1] + bb.y;
            float v2 = acc[mi][ni][2] + bb.x;
            float v3 = acc[mi][ni][3] + bb.y;
            if (APPLY_GELU) {
                v0 = gelu_tanh(v0); v1 = gelu_tanh(v1);
                v2 = gelu_tanh(v2); v3 = gelu_tanh(v3);
            }
            if (OUT_HALF) {
                __half* Ce = (__half*)Cv + (long long)e * cStride;
                __half* p0 = Ce + (long long)rowL * N + n0 + colL;
                *(__half2*)p0 = __floats2half2_rn(v0, v1);
                *(__half2*)(p0 + (long long)8 * N) = __floats2half2_rn(v2, v3);
            } else {
                float* Ce = (float*)Cv + (long long)e * cStride;
                float* p0 = Ce + (long long)rowL * N + n0 + colL;
                *(float2*)p0 = make_float2(v0, v1);
                *(float2*)(p0 + (long long)8 * N) = make_float2(v2, v3);
            }
        }
    }
}

// ---------------- launch ----------------
extern "C" void kernel_launch(void* const* d_in, const int* in_sizes, int n_in,
                              void* d_out, int out_size) {
    (void)in_sizes; (void)n_in; (void)out_size;
    const float* x  = (const float*)d_in[0];
    // d_in[1] = expert_size (uniform T/E by construction; unused)
    const float* w1 = (const float*)d_in[2];
    const float* b1 = (const float*)d_in[3];
    const float* w2 = (const float*)d_in[4];
    const float* b2 = (const float*)d_in[5];
    float* out = (float*)d_out;

    __half *xh, *w1t, *w2t, *h;
    cudaGetSymbolAddress((void**)&xh,  g_xh);
    cudaGetSymbolAddress((void**)&w1t, g_w1t);
    cudaGetSymbolAddress((void**)&w2t, g_w2t);
    cudaGetSymbolAddress((void**)&h,   g_h);

    cudaFuncSetAttribute(gemm_f16_mma<1, 1>,
                         cudaFuncAttributeMaxDynamicSharedMemorySize, SMEM_TOTAL);
    cudaFuncSetAttribute(gemm_f16_mma<0, 0>,
                         cudaFuncAttributeMaxDynamicSharedMemorySize, SMEM_TOTAL);

    // prep: convert X, transpose+convert weights
    cvt_half_kernel<<<(T_TOK * (size_t)D_MODEL) / (256 * 4), 256>>>(x, xh);
    dim3 tb(32, 8);
    transpose_cvt_half<<<dim3(F_FF / 32, D_MODEL / 32, E_EXP), tb>>>(w1, w1t, D_MODEL, F_FF);
    transpose_cvt_half<<<dim3(D_MODEL / 32, F_FF / 32, E_EXP), tb>>>(w2, w2t, F_FF, D_MODEL);

    // GEMM1: H = half(GELU(X @ W1 + b1))
    gemm_f16_mma<1, 1><<<dim3(F_FF / BN, M_PER_E / BM, E_EXP), NTHREADS, SMEM_TOTAL>>>(
        xh, w1t, b1, h,
        /*K=*/D_MODEL, /*N=*/F_FF,
        (long long)M_PER_E * D_MODEL, (long long)F_FF * D_MODEL, F_FF,
        (long long)M_PER_E * F_FF);

    // GEMM2: Y = H @ W2 + b2 (fp32 out)
    gemm_f16_mma<0, 0><<<dim3(D_MODEL / BN, M_PER_E / BM, E_EXP), NTHREADS, SMEM_TOTAL>>>(
        h, w2t, b2, out,
        /*K=*/F_FF, /*N=*/D_MODEL,
        (long long)M_PER_E * F_FF, (long long)D_MODEL * F_FF, D_MODEL,
        (long long)M_PER_E * D_MODEL);
}

// round 6
// speedup vs baseline: 2.1326x; 1.0306x over previous
#include <cuda_runtime.h>
#include <cuda_fp16.h>
#include <cstdint>

// ---------------- problem constants ----------------
#define E_EXP   8
#define T_TOK   16384
#define D_MODEL 1024
#define F_FF    4096
#define M_PER_E (T_TOK / E_EXP)   // 2048

// ---------------- scratch (no allocs allowed) ----------------
__device__ __half g_xh [(size_t)T_TOK * D_MODEL];          //  32MB  fp16 X
__device__ __half g_w1t[(size_t)E_EXP * F_FF * D_MODEL];   //  64MB  [E][F][D] fp16
__device__ __half g_w2t[(size_t)E_EXP * D_MODEL * F_FF];   //  64MB  [E][D][F] fp16
__device__ __half g_h  [(size_t)T_TOK * F_FF];             // 128MB  [T][F]    fp16

// ---------------- helpers ----------------
__device__ __forceinline__ uint32_t smem_u32(const void* p) {
    uint32_t a;
    asm("{ .reg .u64 t; cvta.to.shared.u64 t, %1; cvt.u32.u64 %0, t; }" : "=r"(a) : "l"(p));
    return a;
}
#define CP_ASYNC_16(smem_addr, gmem_ptr) \
    asm volatile("cp.async.cg.shared.global [%0], [%1], 16;" \
                 :: "r"(smem_addr), "l"(gmem_ptr) : "memory")
#define CP_COMMIT() asm volatile("cp.async.commit_group;" ::: "memory")
#define CP_WAIT(n)  asm volatile("cp.async.wait_group %0;" :: "n"(n) : "memory")

__device__ __forceinline__ void ldsm_x4(uint32_t* r, uint32_t addr) {
    asm volatile("ldmatrix.sync.aligned.m8n8.x4.shared.b16 {%0,%1,%2,%3}, [%4];"
                 : "=r"(r[0]), "=r"(r[1]), "=r"(r[2]), "=r"(r[3]) : "r"(addr));
}

__device__ __forceinline__ void mma_f16_16n8k16(float* d, const uint32_t* a, const uint32_t* b) {
    asm volatile(
        "mma.sync.aligned.m16n8k16.row.col.f32.f16.f16.f32 "
        "{%0,%1,%2,%3}, {%4,%5,%6,%7}, {%8,%9}, {%0,%1,%2,%3};"
        : "+f"(d[0]), "+f"(d[1]), "+f"(d[2]), "+f"(d[3])
        : "r"(a[0]), "r"(a[1]), "r"(a[2]), "r"(a[3]), "r"(b[0]), "r"(b[1]));
}

__device__ __forceinline__ float gelu_tanh(float x) {
    float x3 = x * x * x;
    return 0.5f * x * (1.0f + tanhf(0.7978845608028654f * (x + 0.044715f * x3)));
}

// ---------------- prep kernels ----------------
__global__ void cvt_half_kernel(const float* __restrict__ src, __half* __restrict__ dst) {
    size_t i = ((size_t)blockIdx.x * blockDim.x + threadIdx.x) * 4;
    float4 v = *(const float4*)(src + i);
    *(__half2*)(dst + i)     = __floats2half2_rn(v.x, v.y);
    *(__half2*)(dst + i + 2) = __floats2half2_rn(v.z, v.w);
}

// transpose src[z][R][C] fp32 -> dst[z][C][R] fp16
__global__ void transpose_cvt_half(const float* __restrict__ src, __half* __restrict__ dst,
                                   int R, int C) {
    __shared__ float t[32][33];
    size_t base = (size_t)blockIdx.z * R * C;
    int c0 = blockIdx.x * 32, r0 = blockIdx.y * 32;
    int tx = threadIdx.x, ty = threadIdx.y;
#pragma unroll
    for (int i = 0; i < 32; i += 8)
        t[ty + i][tx] = src[base + (size_t)(r0 + ty + i) * C + c0 + tx];
    __syncthreads();
#pragma unroll
    for (int i = 0; i < 32; i += 8)
        dst[base + (size_t)(c0 + ty + i) * R + r0 + tx] = __float2half_rn(t[tx][ty + i]);
}

// ---------------- fp16 mma.sync GEMM ----------------
// C[M,N] = A[M,K] * Bt[N,K]^T  (+bias, optional GELU; OUT_HALF fp16 vs fp32 out)
// BM=128, BN=256, BK=64. 256 threads = 8 warps, warp grid 2(M) x 4(N),
// warp tile 64x64 -> 4 m x 8 n frags of m16n8k16 (32 HMMA : 8 LDSM per k-step).
#define BM 128
#define BN 256
#define BK 64
#define NTHREADS 256
#define NSTG 3
#define A_ST (BM * BK * 2)               // 16384 B / stage
#define B_ST (BN * BK * 2)               // 32768 B / stage
#define SM_B_OFF (NSTG * A_ST)           // 49152
#define SMEM_TOTAL (NSTG * (A_ST + B_ST))  // 147456

template <int APPLY_GELU, int OUT_HALF>
__global__ void __launch_bounds__(NTHREADS, 1)
gemm_f16_mma(const __half* __restrict__ A, const __half* __restrict__ Bt,
             const float* __restrict__ bias, void* __restrict__ Cv,
             int K, int N,
             long long aStride, long long bStride, int biasStride, long long cStride) {
    extern __shared__ char smem[];
    const uint32_t sb = smem_u32(smem);
    const int tid = threadIdx.x;
    const int wid = tid >> 5, lane = tid & 31;
    const int g = lane >> 2, tig = lane & 3;
    const int wm = wid & 1, wn = wid >> 1;         // warp grid 2(M) x 4(N)
    const int e  = blockIdx.z;
    const int m0 = blockIdx.y * BM;
    const int n0 = blockIdx.x * BN;

    const __half* Ae = A  + (long long)e * aStride + (long long)m0 * K;
    const __half* Be = Bt + (long long)e * bStride + (long long)n0 * K;
    const float*  be = bias + (long long)e * biasStride + n0;

    const int NK = K / BK;

    // ---- async copy of one stage (rows of 128B = 8 x 16B chunks, XOR swizzle) ----
    auto issue_stage = [&](int kt, int slot) {
        const __half* ag = Ae + kt * BK;
        const __half* bg = Be + kt * BK;
        uint32_t sA = sb + slot * A_ST;
        uint32_t sB = sb + SM_B_OFF + slot * B_ST;
#pragma unroll
        for (int i = 0; i < 4; i++) {                  // A: 1024 x 16B chunks
            int c = tid + i * NTHREADS;
            int row = c >> 3, ch = c & 7;
            CP_ASYNC_16(sA + row * 128 + ((ch ^ (row & 7)) << 4),
                        ag + (long long)row * K + ch * 8);
        }
#pragma unroll
        for (int i = 0; i < 8; i++) {                  // B: 2048 x 16B chunks
            int c = tid + i * NTHREADS;
            int row = c >> 3, ch = c & 7;
            CP_ASYNC_16(sB + row * 128 + ((ch ^ (row & 7)) << 4),
                        bg + (long long)row * K + ch * 8);
        }
    };

    issue_stage(0, 0); CP_COMMIT();
    if (NK > 1) issue_stage(1, 1);
    CP_COMMIT();

    float acc[4][8][4];
#pragma unroll
    for (int mi = 0; mi < 4; mi++)
#pragma unroll
        for (int ni = 0; ni < 8; ni++)
#pragma unroll
            for (int j = 0; j < 4; j++) acc[mi][ni][j] = 0.0f;

    // ---- hoisted per-lane ldmatrix addressing ----
    const int aRowL = lane & 15;                        // row within m16 tile
    const int aKC   = lane >> 4;                        // k-chunk lo/hi
    const int bRowL = ((lane >> 4) << 3) + (lane & 7);  // row within n16 pair
    const int bKC   = (lane >> 3) & 1;
    uint32_t aChunkOff[4], bChunkOff[4];
#pragma unroll
    for (int ks = 0; ks < 4; ks++) {
        aChunkOff[ks] = (uint32_t)(((2 * ks + aKC) ^ (aRowL & 7)) << 4);
        bChunkOff[ks] = (uint32_t)(((2 * ks + bKC) ^ (lane & 7)) << 4);
    }
    uint32_t aRowOff[4], bRowOff[4];
#pragma unroll
    for (int mi = 0; mi < 4; mi++)
        aRowOff[mi] = (uint32_t)((wm * 64 + mi * 16 + aRowL) * 128);
#pragma unroll
    for (int p = 0; p < 4; p++)
        bRowOff[p] = (uint32_t)((wn * 64 + p * 16 + bRowL) * 128);

    for (int kt = 0; kt < NK; ++kt) {
        CP_WAIT(1);
        __syncthreads();
        if (kt + NSTG - 1 < NK) issue_stage(kt + NSTG - 1, (kt + NSTG - 1) % NSTG);
        CP_COMMIT();

        int slot = kt % NSTG;
        uint32_t aBase = sb + slot * A_ST;
        uint32_t bBase = sb + SM_B_OFF + slot * B_ST;

#pragma unroll
        for (int ks = 0; ks < 4; ks++) {               // 4 x K=16 steps
            uint32_t af[4][4], bf[8][2];
#pragma unroll
            for (int mi = 0; mi < 4; mi++)
                ldsm_x4(af[mi], aBase + aRowOff[mi] + aChunkOff[ks]);
#pragma unroll
            for (int p = 0; p < 4; p++) {
                uint32_t r[4];
                ldsm_x4(r, bBase + bRowOff[p] + bChunkOff[ks]);
                bf[2 * p][0] = r[0]; bf[2 * p][1] = r[1];
                bf[2 * p + 1][0] = r[2]; bf[2 * p + 1][1] = r[3];
            }
#pragma unroll
            for (int mi = 0; mi < 4; mi++)
#pragma unroll
                for (int ni = 0; ni < 8; ni++)
                    mma_f16_16n8k16(acc[mi][ni], af[mi], bf[ni]);
        }
    }

    // ---- epilogue ----
#pragma unroll
    for (int ni = 0; ni < 8; ni++) {
        int colL = wn * 64 + ni * 8 + 2 * tig;
        float2 bb = *(const float2*)(be + colL);
#pragma unroll
        for (int mi = 0; mi < 4; mi++) {
            int rowL = m0 + wm * 64 + mi * 16 + g;
            float v0 = acc[mi][ni][0] + bb.x;
            float v1 = acc[mi][ni][1] + bb.y;
            float v2 = acc[mi][ni][2] + bb.x;
            float v3 = acc[mi][ni][3] + bb.y;
            if (APPLY_GELU) {
                v0 = gelu_tanh(v0); v1 = gelu_tanh(v1);
                v2 = gelu_tanh(v2); v3 = gelu_tanh(v3);
            }
            if (OUT_HALF) {
                __half* Ce = (__half*)Cv + (long long)e * cStride;
                __half* p0 = Ce + (long long)rowL * N + n0 + colL;
                *(__half2*)p0 = __floats2half2_rn(v0, v1);
                *(__half2*)(p0 + (long long)8 * N) = __floats2half2_rn(v2, v3);
            } else {
                float* Ce = (float*)Cv + (long long)e * cStride;
                float* p0 = Ce + (long long)rowL * N + n0 + colL;
                *(float2*)p0 = make_float2(v0, v1);
                *(float2*)(p0 + (long long)8 * N) = make_float2(v2, v3);
            }
        }
    }
}

// ---------------- launch ----------------
extern "C" void kernel_launch(void* const* d_in, const int* in_sizes, int n_in,
                              void* d_out, int out_size) {
    (void)in_sizes; (void)n_in; (void)out_size;
    const float* x  = (const float*)d_in[0];
    // d_in[1] = expert_size (uniform T/E by construction; unused)
    const float* w1 = (const float*)d_in[2];
    const float* b1 = (const float*)d_in[3];
    const float* w2 = (const float*)d_in[4];
    const float* b2 = (const float*)d_in[5];
    float* out = (float*)d_out;

    __half *xh, *w1t, *w2t, *h;
    cudaGetSymbolAddress((void**)&xh,  g_xh);
    cudaGetSymbolAddress((void**)&w1t, g_w1t);
    cudaGetSymbolAddress((void**)&w2t, g_w2t);
    cudaGetSymbolAddress((void**)&h,   g_h);

    cudaFuncSetAttribute(gemm_f16_mma<1, 1>,
                         cudaFuncAttributeMaxDynamicSharedMemorySize, SMEM_TOTAL);
    cudaFuncSetAttribute(gemm_f16_mma<0, 0>,
                         cudaFuncAttributeMaxDynamicSharedMemorySize, SMEM_TOTAL);

    // prep: convert X, transpose+convert weights
    cvt_half_kernel<<<(T_TOK * (size_t)D_MODEL) / (256 * 4), 256>>>(x, xh);
    dim3 tb(32, 8);
    transpose_cvt_half<<<dim3(F_FF / 32, D_MODEL / 32, E_EXP), tb>>>(w1, w1t, D_MODEL, F_FF);
    transpose_cvt_half<<<dim3(D_MODEL / 32, F_FF / 32, E_EXP), tb>>>(w2, w2t, F_FF, D_MODEL);

    // GEMM1: H = half(GELU(X @ W1 + b1))
    gemm_f16_mma<1, 1><<<dim3(F_FF / BN, M_PER_E / BM, E_EXP), NTHREADS, SMEM_TOTAL>>>(
        xh, w1t, b1, h,
        /*K=*/D_MODEL, /*N=*/F_FF,
        (long long)M_PER_E * D_MODEL, (long long)F_FF * D_MODEL, F_FF,
        (long long)M_PER_E * F_FF);

    // GEMM2: Y = H @ W2 + b2 (fp32 out)
    gemm_f16_mma<0, 0><<<dim3(D_MODEL / BN, M_PER_E / BM, E_EXP), NTHREADS, SMEM_TOTAL>>>(
        h, w2t, b2, out,
        /*K=*/F_FF, /*N=*/D_MODEL,
        (long long)M_PER_E * F_FF, (long long)D_MODEL * F_FF, D_MODEL,
        (long long)M_PER_E * D_MODEL);
}